// round 1
// baseline (speedup 1.0000x reference)
#include <cuda_runtime.h>
#include <math.h>

namespace {

constexpr int B = 32, S = 196, T = 64, H = 1024, V = 32000;
constexpr int KQ = 16;   // k-splits for q GEMM (chunks of 64 over K=1024)
constexpr int KG = 6;    // k-splits for gates GEMM (chunks of 512 over K=3072)

typedef unsigned long long ull;

// ---------------- device scratch (static: no allocations allowed) ----------
__device__ float g_h[B * H];
__device__ float g_c[B * H];
__device__ float g_ctx[B * H];
__device__ float g_qpart[KQ * B * H];
__device__ float g_gpart[KG * B * 4 * H];
__device__ float g_Hall[(size_t)T * B * H];   // Hall[m][k], m = t*B + b

// ---------------- packed f32x2 helpers ------------------------------------
__device__ __forceinline__ ull pack2(float x, float y) {
    ull r;
    asm("mov.b64 %0, {%1, %2};" : "=l"(r)
        : "r"(__float_as_uint(x)), "r"(__float_as_uint(y)));
    return r;
}
__device__ __forceinline__ void ffma2(ull &d, ull a, ull b) {
    asm("fma.rn.f32x2 %0, %1, %2, %0;" : "+l"(d) : "l"(a), "l"(b));
}
__device__ __forceinline__ void unpack2(ull v, float &x, float &y) {
    unsigned lo, hi;
    asm("mov.b64 {%0, %1}, %2;" : "=r"(lo), "=r"(hi) : "l"(v));
    x = __uint_as_float(lo);
    y = __uint_as_float(hi);
}

// ---------------- init: zero h, c ------------------------------------------
__global__ void k_init() {
    int i = blockIdx.x * 256 + threadIdx.x;
    if (i < B * H) { g_h[i] = 0.f; g_c[i] = 0.f; }
}

// ---------------- q = h @ attn_W.T  (M=32, N=1024, K=1024, k-split) --------
// grid (16 n-tiles of 64, 16 k-splits of 64), 256 threads
__global__ void k_q(const float* __restrict__ attn_W) {
    const int n0 = blockIdx.x * 64;
    const int ks = blockIdx.y;
    const int k0 = ks * 64;
    const int tid = threadIdx.x;
    __shared__ float hs[B][68];     // hs[b][k]
    __shared__ float Ws[64][68];    // Ws[k][n]

    for (int idx = tid; idx < B * 64; idx += 256) {
        int b = idx >> 6, k = idx & 63;
        hs[b][k] = g_h[b * H + k0 + k];
    }
    for (int idx = tid; idx < 64 * 64; idx += 256) {
        int n = idx >> 6, k = idx & 63;
        Ws[k][n] = attn_W[(size_t)(n0 + n) * H + k0 + k];
    }
    __syncthreads();

    const int bg = tid >> 4;          // 16 groups of 2 batches
    const int ng = tid & 15;          // 16 groups of 4 n
    const int b0 = bg * 2, nn = ng * 4;
    float acc[2][4] = {};
#pragma unroll 8
    for (int k = 0; k < 64; k++) {
        float a0 = hs[b0][k], a1 = hs[b0 + 1][k];
        float4 w = *(const float4*)&Ws[k][nn];
        acc[0][0] += a0 * w.x; acc[0][1] += a0 * w.y;
        acc[0][2] += a0 * w.z; acc[0][3] += a0 * w.w;
        acc[1][0] += a1 * w.x; acc[1][1] += a1 * w.y;
        acc[1][2] += a1 * w.z; acc[1][3] += a1 * w.w;
    }
    float* qp = g_qpart + ks * (B * H);
#pragma unroll
    for (int i = 0; i < 2; i++)
#pragma unroll
        for (int j = 0; j < 4; j++)
            qp[(b0 + i) * H + n0 + nn + j] = acc[i][j];
}

// ---------------- attention: scores -> softmax -> ctx  (1 block per batch) -
__global__ void k_attn(const float* __restrict__ memory) {
    const int b = blockIdx.x;
    const int tid = threadIdx.x;
    __shared__ float q[H];
    __shared__ float sc[224];
    __shared__ float red[256];

    for (int j = tid; j < H; j += 256) {
        float s = 0.f;
#pragma unroll
        for (int p = 0; p < KQ; p++) s += g_qpart[p * (B * H) + b * H + j];
        q[j] = s;
    }
    __syncthreads();

    const float* mb = memory + (size_t)b * S * H;
    const int warp = tid >> 5, lane = tid & 31;
    for (int s = warp; s < S; s += 8) {
        const float* ms = mb + (size_t)s * H;
        float acc = 0.f;
        for (int k = lane; k < H; k += 32) acc += q[k] * ms[k];
#pragma unroll
        for (int o = 16; o; o >>= 1) acc += __shfl_xor_sync(0xffffffffu, acc, o);
        if (lane == 0) sc[s] = acc;
    }
    __syncthreads();

    // max
    red[tid] = (tid < S) ? sc[tid] : -1e30f;
    __syncthreads();
    for (int step = 128; step; step >>= 1) {
        if (tid < step) red[tid] = fmaxf(red[tid], red[tid + step]);
        __syncthreads();
    }
    float mx = red[0];
    __syncthreads();
    // exp + sum
    float e = (tid < S) ? expf(sc[tid] - mx) : 0.f;
    if (tid < S) sc[tid] = e;
    red[tid] = e;
    __syncthreads();
    for (int step = 128; step; step >>= 1) {
        if (tid < step) red[tid] += red[tid + step];
        __syncthreads();
    }
    float inv = 1.f / red[0];

    // ctx: each thread handles columns tid, tid+256, tid+512, tid+768
    float a0 = 0.f, a1 = 0.f, a2 = 0.f, a3 = 0.f;
    for (int s = 0; s < S; s++) {
        float w = sc[s];
        const float* ms = mb + (size_t)s * H + tid;
        a0 += w * ms[0];
        a1 += w * ms[256];
        a2 += w * ms[512];
        a3 += w * ms[768];
    }
    g_ctx[b * H + tid]       = a0 * inv;
    g_ctx[b * H + tid + 256] = a1 * inv;
    g_ctx[b * H + tid + 512] = a2 * inv;
    g_ctx[b * H + tid + 768] = a3 * inv;
}

// ---------------- gates GEMM: [emb_t | ctx | h] (K=3072) -> 4096 gates -----
// grid (32 n-tiles of 128, 6 k-chunks of 512), 256 threads; f32x2 packed
__global__ void k_gates(const float* __restrict__ W_ih, const float* __restrict__ W_hh,
                        const float* __restrict__ emb_table,
                        const int* __restrict__ captions, int t) {
    const int n0 = blockIdx.x * 128;
    const int c  = blockIdx.y;          // chunk: 0,1=emb(W_ih) 2,3=ctx(W_ih) 4,5=h(W_hh)
    const int tid = threadIdx.x;
    __shared__ float xs[B][33];         // xs[b][k], 32 k per tile
    __shared__ float Ws[32][132];       // Ws[k][n]
    __shared__ const float* xbase[B];

    if (tid < B) {
        int b = tid;
        const float* p;
        if (c < 2)      p = emb_table + (size_t)captions[b * T + t] * H + c * 512;
        else if (c < 4) p = g_ctx + b * H + (c - 2) * 512;
        else            p = g_h + b * H + (c - 4) * 512;
        xbase[b] = p;
    }
    const float* W = (c < 4) ? W_ih : W_hh;
    const int ldw  = (c < 4) ? 2 * H : H;
    const int col0 = (c < 4) ? c * 512 : (c - 4) * 512;
    __syncthreads();

    const int bg = tid >> 5;            // warp id: 8 groups of 4 batches
    const int ng = tid & 31;            // 32 groups of 4 n
    const int bb = bg * 4, nn = ng * 4;
    ull acc[4][2] = {};

    for (int kk = 0; kk < 512; kk += 32) {
        __syncthreads();
        {   // xs fill: 32x32, one float4 per thread
            int idx = tid * 4;
            int b = idx >> 5, k = idx & 31;
            float4 v = *(const float4*)(xbase[b] + kk + k);
            xs[b][k] = v.x; xs[b][k + 1] = v.y; xs[b][k + 2] = v.z; xs[b][k + 3] = v.w;
        }
        // Ws fill: 128n x 32k, coalesced along k
        for (int idx = tid; idx < 128 * 32; idx += 256) {
            int n = idx >> 5, k = idx & 31;
            Ws[k][n] = W[(size_t)(n0 + n) * ldw + col0 + kk + k];
        }
        __syncthreads();
#pragma unroll 8
        for (int k = 0; k < 32; k++) {
            ulonglong2 wv = *(const ulonglong2*)&Ws[k][nn];
            float a0 = xs[bb][k], a1 = xs[bb + 1][k];
            float a2 = xs[bb + 2][k], a3 = xs[bb + 3][k];
            ull p0 = pack2(a0, a0), p1 = pack2(a1, a1);
            ull p2 = pack2(a2, a2), p3 = pack2(a3, a3);
            ffma2(acc[0][0], p0, wv.x); ffma2(acc[0][1], p0, wv.y);
            ffma2(acc[1][0], p1, wv.x); ffma2(acc[1][1], p1, wv.y);
            ffma2(acc[2][0], p2, wv.x); ffma2(acc[2][1], p2, wv.y);
            ffma2(acc[3][0], p3, wv.x); ffma2(acc[3][1], p3, wv.y);
        }
    }
    float* gp = g_gpart + c * (B * 4 * H);
#pragma unroll
    for (int i = 0; i < 4; i++) {
        float v0x, v0y, v1x, v1y;
        unpack2(acc[i][0], v0x, v0y);
        unpack2(acc[i][1], v1x, v1y);
        float* row = gp + (bb + i) * 4 * H + n0 + nn;
        row[0] = v0x; row[1] = v0y; row[2] = v1x; row[3] = v1y;
    }
}

// ---------------- LSTM cell pointwise + state update + Hall store ----------
__global__ void k_cell(const float* __restrict__ b_ih, const float* __restrict__ b_hh, int t) {
    int idx = blockIdx.x * 256 + threadIdx.x;
    if (idx >= B * H) return;
    int b = idx >> 10, j = idx & (H - 1);
    float gi = 0.f, gf = 0.f, gg = 0.f, go = 0.f;
#pragma unroll
    for (int p = 0; p < KG; p++) {
        const float* base = g_gpart + p * (B * 4 * H) + b * 4 * H;
        gi += base[j];
        gf += base[j + H];
        gg += base[j + 2 * H];
        go += base[j + 3 * H];
    }
    gi += b_ih[j] + b_hh[j];
    gf += b_ih[j + H] + b_hh[j + H];
    gg += b_ih[j + 2 * H] + b_hh[j + 2 * H];
    go += b_ih[j + 3 * H] + b_hh[j + 3 * H];
    float iv = 1.f / (1.f + expf(-gi));
    float fv = 1.f / (1.f + expf(-gf));
    float gv = tanhf(gg);
    float ov = 1.f / (1.f + expf(-go));
    float cn = fv * g_c[idx] + iv * gv;
    float hn = ov * tanhf(cn);
    g_c[idx] = cn;
    g_h[idx] = hn;
    g_Hall[((size_t)t * B + b) * H + j] = hn;   // m = t*B + b
}

// ---------------- batched logits GEMM: Hall[2048,1024] @ W_out.T -> [.,32000]
// 128x128 block tile, 8x8 per thread (n packed as f32x2 pairs), KT=8
__global__ void __launch_bounds__(256) k_logits(const float* __restrict__ Wout,
                                                const float* __restrict__ bout,
                                                float* __restrict__ out) {
    const int n0 = blockIdx.x * 128;
    const int m0 = blockIdx.y * 128;
    const int tid = threadIdx.x;
    __shared__ float As[8][128];   // As[k][m]
    __shared__ float Bs[8][128];   // Bs[k][n]

    const int lm = tid >> 1, lk = (tid & 1) * 4;
    const float* Ap = g_Hall + (size_t)(m0 + lm) * H + lk;
    const float* Bp = Wout   + (size_t)(n0 + lm) * H + lk;

    const int ty = tid >> 4, tx = tid & 15;
    const int ms = ty * 8, ns = tx * 8;
    ull acc[8][4] = {};

    for (int k0 = 0; k0 < H; k0 += 8) {
        float4 av = *(const float4*)(Ap + k0);
        float4 bv = *(const float4*)(Bp + k0);
        __syncthreads();
        As[lk][lm] = av.x; As[lk + 1][lm] = av.y; As[lk + 2][lm] = av.z; As[lk + 3][lm] = av.w;
        Bs[lk][lm] = bv.x; Bs[lk + 1][lm] = bv.y; Bs[lk + 2][lm] = bv.z; Bs[lk + 3][lm] = bv.w;
        __syncthreads();
#pragma unroll
        for (int kk = 0; kk < 8; kk++) {
            float4 a0 = *(const float4*)&As[kk][ms];
            float4 a1 = *(const float4*)&As[kk][ms + 4];
            ulonglong2 b0 = *(const ulonglong2*)&Bs[kk][ns];
            ulonglong2 b1 = *(const ulonglong2*)&Bs[kk][ns + 4];
            float a[8] = {a0.x, a0.y, a0.z, a0.w, a1.x, a1.y, a1.z, a1.w};
            ull bp[4]  = {b0.x, b0.y, b1.x, b1.y};
#pragma unroll
            for (int i = 0; i < 8; i++) {
                ull ap = pack2(a[i], a[i]);
                ffma2(acc[i][0], ap, bp[0]);
                ffma2(acc[i][1], ap, bp[1]);
                ffma2(acc[i][2], ap, bp[2]);
                ffma2(acc[i][3], ap, bp[3]);
            }
        }
    }
#pragma unroll
    for (int i = 0; i < 8; i++) {
        int m  = m0 + ms + i;
        int tt = m >> 5, b = m & 31;                        // m = t*B + b
        float* orow = out + ((size_t)(b * T + tt)) * V + n0 + ns;
        const float* br = bout + n0 + ns;
#pragma unroll
        for (int j = 0; j < 4; j++) {
            float vx, vy;
            unpack2(acc[i][j], vx, vy);
            orow[2 * j]     = vx + br[2 * j];
            orow[2 * j + 1] = vy + br[2 * j + 1];
        }
    }
}

// ---------------- final h, c copy into out tail ----------------------------
__global__ void k_final(float* __restrict__ dst) {
    int i = blockIdx.x * 256 + threadIdx.x;
    if (i < B * H) {
        dst[i]         = g_h[i];
        dst[B * H + i] = g_c[i];
    }
}

} // namespace

extern "C" void kernel_launch(void* const* d_in, const int* in_sizes, int n_in,
                              void* d_out, int out_size) {
    const float* memory   = (const float*)d_in[0];
    const int*   captions = (const int*)d_in[1];
    const float* emb      = (const float*)d_in[2];
    const float* attn_W   = (const float*)d_in[3];
    const float* W_ih     = (const float*)d_in[4];
    const float* W_hh     = (const float*)d_in[5];
    const float* b_ih     = (const float*)d_in[6];
    const float* b_hh     = (const float*)d_in[7];
    const float* W_out    = (const float*)d_in[8];
    const float* b_out    = (const float*)d_in[9];
    float* out = (float*)d_out;

    k_init<<<(B * H + 255) / 256, 256>>>();
    for (int t = 0; t < T; t++) {
        k_q<<<dim3(16, KQ), 256>>>(attn_W);
        k_attn<<<B, 256>>>(memory);
        k_gates<<<dim3(32, KG), 256>>>(W_ih, W_hh, emb, captions, t);
        k_cell<<<(B * H + 255) / 256, 256>>>(b_ih, b_hh, t);
    }
    k_logits<<<dim3(V / 128, (T * B) / 128), 256>>>(W_out, b_out, out);
    if (out_size >= B * T * V + 2 * B * H)
        k_final<<<(B * H + 255) / 256, 256>>>(out + (size_t)B * T * V);
}